// round 8
// baseline (speedup 1.0000x reference)
#include <cuda_runtime.h>
#include <cuda_bf16.h>
#include <cstddef>

#define N 4096
#define N4 (N / 4)
#define ROWS_PER_BLK 64
#define CBLK4 256          // float4-columns per block (256 threads x 1)

// ---------------- device scratch (no allocations allowed) ----------------
__device__ __align__(16) float g_bufA[N];
__device__ __align__(16) float g_bufB[N];
__device__ __align__(16) float g_r[N];
__device__ __align__(16) float g_r2[N];
__device__ float  g_sums[1];               // sum(input), written by pass 1
__device__ __align__(16) float4 g_col[N];  // per-column: {decay, P, Q, currb}
__device__ float  g_actX[N];
__device__ float  g_Bn[N];
__device__ float  g_prevb[N];
__device__ float  g_diag[N];

// ---------------- dual matvec: warp-per-row, 8 rows per block -------------
// yx[row] = b[row] + 0.5*(J x)_row ; yr[row] = (J r)_row (r == ones if first)
// grid = N/8 = 512 blocks, shuffle-only reduction.
// first: block0/warp0 also accumulates sum(input) -> g_sums[0].
// last:  lane 0 runs the entire per-element epilogue for its row.
__global__ void k_pass(const float* __restrict__ J, const float* __restrict__ x,
                       const float* __restrict__ r, const float* __restrict__ b,
                       float* __restrict__ yx, float* __restrict__ yr,
                       int first, int last,
                       const float* __restrict__ Bpos, const float* __restrict__ Bneg,
                       const float* __restrict__ etainv, const float* __restrict__ Tcnt,
                       const int* __restrict__ prev, const int* __restrict__ curr,
                       float* __restrict__ out_act, float* __restrict__ out_Bpos,
                       float* __restrict__ out_Bneg, float* __restrict__ out_eta,
                       float* __restrict__ out_Tcnt) {
    int warp = threadIdx.x >> 5;
    int lane = threadIdx.x & 31;
    int row = blockIdx.x * 8 + warp;
    const float4* Jr = reinterpret_cast<const float4*>(J + (size_t)row * N);
    const float4* x4 = reinterpret_cast<const float4*>(x);
    const float4* r4 = reinterpret_cast<const float4*>(r);
    bool sum_warp = (first && row == 0);
    float sx = 0.0f, sr = 0.0f, si = 0.0f;
#pragma unroll 8
    for (int k = 0; k < 32; k++) {
        int idx = lane + (k << 5);
        float4 jv = Jr[idx];
        float4 xv = x4[idx];
        sx += jv.x * xv.x + jv.y * xv.y + jv.z * xv.z + jv.w * xv.w;
        if (first) {
            sr += jv.x + jv.y + jv.z + jv.w;
        } else {
            float4 rv = r4[idx];
            sr += jv.x * rv.x + jv.y * rv.y + jv.z * rv.z + jv.w * rv.w;
        }
        if (sum_warp) si += xv.x + xv.y + xv.z + xv.w;
    }
#pragma unroll
    for (int off = 16; off > 0; off >>= 1) {
        sx += __shfl_down_sync(0xffffffffu, sx, off);
        sr += __shfl_down_sync(0xffffffffu, sr, off);
        if (sum_warp) si += __shfl_down_sync(0xffffffffu, si, off);
    }
    if (lane != 0) return;

    if (sum_warp) g_sums[0] = si;

    float a = b[row] + 0.5f * sx;
    float rv = sr;

    if (!last) {
        yx[row] = a;
        yr[row] = rv;
        return;
    }

    // ---------------- fused per-element epilogue ----------------
    // alpha analytic: column-stochastic J => sum(a3)=1.875*S, sum(r)=N
    //                 alpha = (1.875S - 2S)/N = -0.125*S/N
    int i = row;
    float alpha = -0.125f * g_sums[0] * (1.0f / (float)N);
    float act = a - alpha * rv;
    out_act[i] = act;

    float X = fminf(fmaxf(act, 0.0f), 1.0f);
    float act01 = (X >= 0.99f) ? 1.0f : 0.0f;

    const float lrp = (float)(0.1 / 0.12);
    float Bp = fminf((1.0f - lrp) * Bpos[i] + lrp * 7.0f * act01, 6.0f);
    float Bn = 0.9f * Bneg[i];  // A_NEG = 0, lr_n = 0.1

    float ei = (float)prev[i] + 0.99f * etainv[i];
    out_Bpos[i] = Bp;
    out_Bneg[i] = Bn;
    out_eta[i]  = ei;

    float prevb = (prev[i] > 0) ? 1.0f : 0.0f;
    out_Tcnt[i] = 0.99f * Tcnt[i] + prevb;

    float actX = (X < 0.99f) ? 0.0f : X;
    float Bpe = (Bp < 0.0f) ? 0.0f : Bp;   // UPDATE_MIN = 0
    float Bne = (Bn < 0.0f) ? 0.0f : Bn;
    float eta = 1.0f / ei;
    bool updated = (prev[i] == 1);

    float decay = updated ? (1.0f - eta) : 1.0f;
    float P = updated ? 1.008f * eta * Bpe : 0.0f;    // 0.1 * 10.08
    float Q = updated ? 1.008f * eta * actX : 0.0f;
    float currb = (curr[i] > 0) ? 1.0f : 0.0f;
    g_col[i] = make_float4(decay, P, Q, currb);
    g_actX[i] = actX;
    g_Bn[i] = Bne;
    g_prevb[i] = prevb;
    g_diag[i] = updated ? eta * 0.165f * actX * Bpe : 0.0f;  // 0.1 * 1.65
}

// ---------------- fused N^2 kernel: J_n and real_T_tilde_n -----------------
// Column-stationary layout: thread owns 4 fixed columns (coefficients in
// REGISTERS, loaded once), loops over 64 rows. Row scalars staged in smem.
// This removes the 4x g_col L1 amplification that limited the row-major form.
__global__ void k_big(const float* __restrict__ J, const float* __restrict__ Tt,
                      float* __restrict__ outJ, float* __restrict__ outT) {
    int q = blockIdx.x * CBLK4 + threadIdx.x;   // this thread's float4 column
    int r0 = blockIdx.y * ROWS_PER_BLK;

    __shared__ float s_actX[ROWS_PER_BLK], s_Bn[ROWS_PER_BLK],
                     s_prevb[ROWS_PER_BLK], s_diag[ROWS_PER_BLK];
    {
        int t = threadIdx.x;
        if (t < ROWS_PER_BLK)            s_actX[t]                 = g_actX[r0 + t];
        else if (t < 2 * ROWS_PER_BLK)   s_Bn[t - ROWS_PER_BLK]    = g_Bn[r0 + t - ROWS_PER_BLK];
        else if (t < 3 * ROWS_PER_BLK)   s_prevb[t - 2*ROWS_PER_BLK] = g_prevb[r0 + t - 2*ROWS_PER_BLK];
        else                             s_diag[t - 3*ROWS_PER_BLK]  = g_diag[r0 + t - 3*ROWS_PER_BLK];
    }
    __syncthreads();

    // column coefficients: 4 columns, in registers for the whole block
    int j0 = q << 2;
    float4 c0 = g_col[j0 + 0];
    float4 c1 = g_col[j0 + 1];
    float4 c2 = g_col[j0 + 2];
    float4 c3 = g_col[j0 + 3];

    const float4* J4 = reinterpret_cast<const float4*>(J);
    const float4* T4 = reinterpret_cast<const float4*>(Tt);
    float4* oJ = reinterpret_cast<float4*>(outJ);
    float4* oT = reinterpret_cast<float4*>(outT);

#pragma unroll 4
    for (int rr = 0; rr < ROWS_PER_BLK; rr++) {
        int i = r0 + rr;
        float actXi = s_actX[rr];
        float Bni   = s_Bn[rr];
        float prevbi= s_prevb[rr];
        size_t off = (size_t)i * N4 + q;
        float4 jv = J4[off];
        float4 tv = __ldcs(T4 + off);

        float4 rj, rt;
        rj.x = fminf(fmaxf(c0.x * jv.x + actXi * c0.y + Bni * c0.z, 0.0f), 1.0f);
        rj.y = fminf(fmaxf(c1.x * jv.y + actXi * c1.y + Bni * c1.z, 0.0f), 1.0f);
        rj.z = fminf(fmaxf(c2.x * jv.z + actXi * c2.y + Bni * c2.z, 0.0f), 1.0f);
        rj.w = fminf(fmaxf(c3.x * jv.w + actXi * c3.y + Bni * c3.z, 0.0f), 1.0f);
        rt.x = 0.99f * tv.x + prevbi * c0.w;
        rt.y = 0.99f * tv.y + prevbi * c1.w;
        rt.z = 0.99f * tv.z + prevbi * c2.w;
        rt.w = 0.99f * tv.w + prevbi * c3.w;

        if ((i >> 2) == q) {  // diagonal element lives in this thread's float4
            int c = i & 3;
            float Jx = (&jv.x)[c];
            float dec = (c == 0) ? c0.x : (c == 1) ? c1.x : (c == 2) ? c2.x : c3.x;
            (&rj.x)[c] = fminf(fmaxf(dec * Jx + s_diag[rr], 0.0f), 1.0f);
        }
        __stcs(oJ + off, rj);
        __stcs(oT + off, rt);
    }
}

// ---------------- host launcher ----------------
extern "C" void kernel_launch(void* const* d_in, const int* in_sizes, int n_in,
                              void* d_out, int out_size) {
    const float* input  = (const float*)d_in[0];
    const float* J      = (const float*)d_in[1];
    const float* Bpos   = (const float*)d_in[2];
    const float* Bneg   = (const float*)d_in[3];
    const float* etainv = (const float*)d_in[4];
    const float* Tt     = (const float*)d_in[5];
    const float* Tcnt   = (const float*)d_in[6];
    const int*   prev   = (const int*)d_in[7];
    const int*   curr   = (const int*)d_in[8];

    float* out = (float*)d_out;
    float* out_act  = out;                         // N
    float* out_J    = out + N;                     // N*N
    float* out_Bpos = out_J + (size_t)N * N;       // N
    float* out_Bneg = out_Bpos + N;                // N
    float* out_eta  = out_Bneg + N;                // N
    float* out_Tt   = out_eta + N;                 // N*N
    float* out_Tcnt = out_Tt + (size_t)N * N;      // N

    float *dA, *dB, *dR, *dR2;
    cudaGetSymbolAddress((void**)&dA, g_bufA);
    cudaGetSymbolAddress((void**)&dB, g_bufB);
    cudaGetSymbolAddress((void**)&dR, g_r);
    cudaGetSymbolAddress((void**)&dR2, g_r2);

    // 3 joint passes: x_{k+1} = input + 0.5*J*x_k (x_0 = input),
    //                 r_{k+1} = J*r_k            (r_0 = ones, implicit pass 1).
    // Pass 1 also emits sum(input). Pass 3 fuses the per-element epilogue.
    k_pass<<<N / 8, 256>>>(J, input, dR, input, dA, dR, 1, 0,
                           nullptr, nullptr, nullptr, nullptr, nullptr, nullptr,
                           nullptr, nullptr, nullptr, nullptr, nullptr);
    k_pass<<<N / 8, 256>>>(J, dA, dR, input, dB, dR2, 0, 0,
                           nullptr, nullptr, nullptr, nullptr, nullptr, nullptr,
                           nullptr, nullptr, nullptr, nullptr, nullptr);
    k_pass<<<N / 8, 256>>>(J, dB, dR2, input, dA, dR, 0, 1,
                           Bpos, Bneg, etainv, Tcnt, prev, curr,
                           out_act, out_Bpos, out_Bneg, out_eta, out_Tcnt);

    dim3 grid(N4 / CBLK4, N / ROWS_PER_BLK);   // (4, 64) = 256 blocks
    k_big<<<grid, CBLK4>>>(J, Tt, out_J, out_Tt);
}

// round 9
// speedup vs baseline: 1.0742x; 1.0742x over previous
#include <cuda_runtime.h>
#include <cuda_bf16.h>
#include <cstddef>

#define N 4096
#define N4 (N / 4)
#define ROWS_PER_BLK 8
#define CBLK4 256          // float4-columns per block (256 threads)

// ---------------- device scratch (no allocations allowed) ----------------
__device__ __align__(16) float g_bufA[N];
__device__ __align__(16) float g_bufB[N];
__device__ __align__(16) float g_r[N];
__device__ __align__(16) float g_r2[N];
__device__ float  g_sums[1];               // sum(input), written by pass 1
__device__ __align__(16) float4 g_col[N];  // per-column: {decay, P, Q, currb}
__device__ float  g_actX[N];
__device__ float  g_Bn[N];
__device__ float  g_prevb[N];
__device__ float  g_diag[N];

// ---------------- dual matvec: warp-per-row, 8 rows per block -------------
// yx[row] = b[row] + 0.5*(J x)_row ; yr[row] = (J r)_row (r == ones if first)
// grid = N/8 = 512 blocks, shuffle-only reduction.
// first: block0/warp0 also accumulates sum(input) -> g_sums[0].
// last:  lane 0 runs the entire per-element epilogue for its row.
__global__ void k_pass(const float* __restrict__ J, const float* __restrict__ x,
                       const float* __restrict__ r, const float* __restrict__ b,
                       float* __restrict__ yx, float* __restrict__ yr,
                       int first, int last,
                       const float* __restrict__ Bpos, const float* __restrict__ Bneg,
                       const float* __restrict__ etainv, const float* __restrict__ Tcnt,
                       const int* __restrict__ prev, const int* __restrict__ curr,
                       float* __restrict__ out_act, float* __restrict__ out_Bpos,
                       float* __restrict__ out_Bneg, float* __restrict__ out_eta,
                       float* __restrict__ out_Tcnt) {
    int warp = threadIdx.x >> 5;
    int lane = threadIdx.x & 31;
    int row = blockIdx.x * 8 + warp;
    const float4* Jr = reinterpret_cast<const float4*>(J + (size_t)row * N);
    const float4* x4 = reinterpret_cast<const float4*>(x);
    const float4* r4 = reinterpret_cast<const float4*>(r);
    bool sum_warp = (first && row == 0);
    float sx = 0.0f, sr = 0.0f, si = 0.0f;
#pragma unroll 8
    for (int k = 0; k < 32; k++) {
        int idx = lane + (k << 5);
        float4 jv = Jr[idx];
        float4 xv = x4[idx];
        sx += jv.x * xv.x + jv.y * xv.y + jv.z * xv.z + jv.w * xv.w;
        if (first) {
            sr += jv.x + jv.y + jv.z + jv.w;
        } else {
            float4 rv = r4[idx];
            sr += jv.x * rv.x + jv.y * rv.y + jv.z * rv.z + jv.w * rv.w;
        }
        if (sum_warp) si += xv.x + xv.y + xv.z + xv.w;
    }
#pragma unroll
    for (int off = 16; off > 0; off >>= 1) {
        sx += __shfl_down_sync(0xffffffffu, sx, off);
        sr += __shfl_down_sync(0xffffffffu, sr, off);
        if (sum_warp) si += __shfl_down_sync(0xffffffffu, si, off);
    }
    if (lane != 0) return;

    if (sum_warp) g_sums[0] = si;

    float a = b[row] + 0.5f * sx;
    float rv = sr;

    if (!last) {
        yx[row] = a;
        yr[row] = rv;
        return;
    }

    // ---------------- fused per-element epilogue ----------------
    // alpha analytic: column-stochastic J => sum(a3)=1.875*S, sum(r)=N
    //                 alpha = (1.875S - 2S)/N = -0.125*S/N
    int i = row;
    float alpha = -0.125f * g_sums[0] * (1.0f / (float)N);
    float act = a - alpha * rv;
    out_act[i] = act;

    float X = fminf(fmaxf(act, 0.0f), 1.0f);
    float act01 = (X >= 0.99f) ? 1.0f : 0.0f;

    const float lrp = (float)(0.1 / 0.12);
    float Bp = fminf((1.0f - lrp) * Bpos[i] + lrp * 7.0f * act01, 6.0f);
    float Bn = 0.9f * Bneg[i];  // A_NEG = 0, lr_n = 0.1

    float ei = (float)prev[i] + 0.99f * etainv[i];
    out_Bpos[i] = Bp;
    out_Bneg[i] = Bn;
    out_eta[i]  = ei;

    float prevb = (prev[i] > 0) ? 1.0f : 0.0f;
    out_Tcnt[i] = 0.99f * Tcnt[i] + prevb;

    float actX = (X < 0.99f) ? 0.0f : X;
    float Bpe = (Bp < 0.0f) ? 0.0f : Bp;   // UPDATE_MIN = 0
    float Bne = (Bn < 0.0f) ? 0.0f : Bn;
    float eta = 1.0f / ei;
    bool updated = (prev[i] == 1);

    float decay = updated ? (1.0f - eta) : 1.0f;
    float P = updated ? 1.008f * eta * Bpe : 0.0f;    // 0.1 * 10.08
    float Q = updated ? 1.008f * eta * actX : 0.0f;
    float currb = (curr[i] > 0) ? 1.0f : 0.0f;
    g_col[i] = make_float4(decay, P, Q, currb);
    g_actX[i] = actX;
    g_Bn[i] = Bne;
    g_prevb[i] = prevb;
    g_diag[i] = updated ? eta * 0.165f * actX * Bpe : 0.0f;  // 0.1 * 1.65
}

// ---------------- fused N^2 kernel: J_n and real_T_tilde_n -----------------
// Column-stationary: thread owns 4 fixed columns (coeffs in registers, read
// once per 8 rows -> 1/8 of J traffic), loops over an 8-row tile.
// grid = (4, 512) = 2048 blocks -> ~14 blocks/SM for high occupancy + MLP.
__global__ void k_big(const float* __restrict__ J, const float* __restrict__ Tt,
                      float* __restrict__ outJ, float* __restrict__ outT) {
    int q = blockIdx.x * CBLK4 + threadIdx.x;   // this thread's float4 column
    int r0 = blockIdx.y * ROWS_PER_BLK;

    __shared__ float s_actX[ROWS_PER_BLK], s_Bn[ROWS_PER_BLK],
                     s_prevb[ROWS_PER_BLK], s_diag[ROWS_PER_BLK];
    if (threadIdx.x < 4 * ROWS_PER_BLK) {
        int t = threadIdx.x;
        int sel = t >> 3;          // which array
        int rr = t & 7;
        float v;
        if (sel == 0)      v = g_actX[r0 + rr];
        else if (sel == 1) v = g_Bn[r0 + rr];
        else if (sel == 2) v = g_prevb[r0 + rr];
        else               v = g_diag[r0 + rr];
        if (sel == 0)      s_actX[rr] = v;
        else if (sel == 1) s_Bn[rr] = v;
        else if (sel == 2) s_prevb[rr] = v;
        else               s_diag[rr] = v;
    }
    __syncthreads();

    // column coefficients: 4 columns, in registers for the whole tile
    int j0 = q << 2;
    float4 c0 = g_col[j0 + 0];
    float4 c1 = g_col[j0 + 1];
    float4 c2 = g_col[j0 + 2];
    float4 c3 = g_col[j0 + 3];

    const float4* J4 = reinterpret_cast<const float4*>(J);
    const float4* T4 = reinterpret_cast<const float4*>(Tt);
    float4* oJ = reinterpret_cast<float4*>(outJ);
    float4* oT = reinterpret_cast<float4*>(outT);

    size_t base = (size_t)r0 * N4 + q;
#pragma unroll
    for (int rr = 0; rr < ROWS_PER_BLK; rr++) {
        int i = r0 + rr;
        float actXi  = s_actX[rr];
        float Bni    = s_Bn[rr];
        float prevbi = s_prevb[rr];
        size_t off = base + (size_t)rr * N4;
        float4 jv = J4[off];
        float4 tv = __ldcs(T4 + off);

        float4 rj, rt;
        rj.x = fminf(fmaxf(c0.x * jv.x + actXi * c0.y + Bni * c0.z, 0.0f), 1.0f);
        rj.y = fminf(fmaxf(c1.x * jv.y + actXi * c1.y + Bni * c1.z, 0.0f), 1.0f);
        rj.z = fminf(fmaxf(c2.x * jv.z + actXi * c2.y + Bni * c2.z, 0.0f), 1.0f);
        rj.w = fminf(fmaxf(c3.x * jv.w + actXi * c3.y + Bni * c3.z, 0.0f), 1.0f);
        rt.x = 0.99f * tv.x + prevbi * c0.w;
        rt.y = 0.99f * tv.y + prevbi * c1.w;
        rt.z = 0.99f * tv.z + prevbi * c2.w;
        rt.w = 0.99f * tv.w + prevbi * c3.w;

        if ((i >> 2) == q) {  // diagonal element lives in this thread's float4
            int c = i & 3;
            float Jx = (&jv.x)[c];
            float dec = (c == 0) ? c0.x : (c == 1) ? c1.x : (c == 2) ? c2.x : c3.x;
            (&rj.x)[c] = fminf(fmaxf(dec * Jx + s_diag[rr], 0.0f), 1.0f);
        }
        __stcs(oJ + off, rj);
        __stcs(oT + off, rt);
    }
}

// ---------------- host launcher ----------------
extern "C" void kernel_launch(void* const* d_in, const int* in_sizes, int n_in,
                              void* d_out, int out_size) {
    const float* input  = (const float*)d_in[0];
    const float* J      = (const float*)d_in[1];
    const float* Bpos   = (const float*)d_in[2];
    const float* Bneg   = (const float*)d_in[3];
    const float* etainv = (const float*)d_in[4];
    const float* Tt     = (const float*)d_in[5];
    const float* Tcnt   = (const float*)d_in[6];
    const int*   prev   = (const int*)d_in[7];
    const int*   curr   = (const int*)d_in[8];

    float* out = (float*)d_out;
    float* out_act  = out;                         // N
    float* out_J    = out + N;                     // N*N
    float* out_Bpos = out_J + (size_t)N * N;       // N
    float* out_Bneg = out_Bpos + N;                // N
    float* out_eta  = out_Bneg + N;                // N
    float* out_Tt   = out_eta + N;                 // N*N
    float* out_Tcnt = out_Tt + (size_t)N * N;      // N

    float *dA, *dB, *dR, *dR2;
    cudaGetSymbolAddress((void**)&dA, g_bufA);
    cudaGetSymbolAddress((void**)&dB, g_bufB);
    cudaGetSymbolAddress((void**)&dR, g_r);
    cudaGetSymbolAddress((void**)&dR2, g_r2);

    // 3 joint passes: x_{k+1} = input + 0.5*J*x_k (x_0 = input),
    //                 r_{k+1} = J*r_k            (r_0 = ones, implicit pass 1).
    // Pass 1 also emits sum(input). Pass 3 fuses the per-element epilogue.
    k_pass<<<N / 8, 256>>>(J, input, dR, input, dA, dR, 1, 0,
                           nullptr, nullptr, nullptr, nullptr, nullptr, nullptr,
                           nullptr, nullptr, nullptr, nullptr, nullptr);
    k_pass<<<N / 8, 256>>>(J, dA, dR, input, dB, dR2, 0, 0,
                           nullptr, nullptr, nullptr, nullptr, nullptr, nullptr,
                           nullptr, nullptr, nullptr, nullptr, nullptr);
    k_pass<<<N / 8, 256>>>(J, dB, dR2, input, dA, dR, 0, 1,
                           Bpos, Bneg, etainv, Tcnt, prev, curr,
                           out_act, out_Bpos, out_Bneg, out_eta, out_Tcnt);

    dim3 grid(N4 / CBLK4, N / ROWS_PER_BLK);   // (4, 512) = 2048 blocks
    k_big<<<grid, CBLK4>>>(J, Tt, out_J, out_Tt);
}